// round 15
// baseline (speedup 1.0000x reference)
#include <cuda_runtime.h>
#include <stdint.h>

#define BB      8
#define NN      197
#define DIM     64
#define HEADS   2
#define DH      32
#define INNER   64
#define NU      1122
#define PCAP    200
#define CHUNK   16
#define MAXWORK 4200
#define GEMMGRID 3584
#define SCALE   0.17677669529663687f

// dynamic smem layout for k_gemm (float words)
#define SW_OFF   0                    // 4096 floats (16 KB)
#define SX_OFF   4096                 // 128*68 = 8704 floats
#define SA_OFF   12800                // 256 floats
#define SP_OFF   13056                // 16 ints (as float words)
#define GEMM_SMEM ((SP_OFF + 16) * 4) // 52288 bytes

// ---------------- scratch ----------------
__device__ float g_xn[BB * NN * DIM];
__device__ float g_q [BB * HEADS * NN * DH];
__device__ float g_k [BB * HEADS * NN * DH];
__device__ float g_attn[NN * BB * HEADS * NN];          // [n][b][h][m]
__device__ int   g_cnt[NU];
__device__ int   g_pairs[NU * PCAP];                    // (n<<8)|m
__device__ int2  g_work[MAXWORK];                       // (u, start)
__device__ int   g_nwork;
__device__ float g_z[(size_t)NN * NN * BB * INNER];     // [n][m][b][e], 79.5MB

// ---------------- helpers ----------------
__device__ __forceinline__ uint64_t dup2(float v) {
    uint64_t r; asm("mov.b64 %0, {%1, %1};" : "=l"(r) : "f"(v)); return r;
}
__device__ __forceinline__ uint64_t pk2(float a, float b) {
    uint64_t r; asm("mov.b64 %0, {%1, %2};" : "=l"(r) : "f"(a), "f"(b)); return r;
}
__device__ __forceinline__ void fma2(uint64_t& d, uint64_t a, uint64_t b) {
    asm("fma.rn.f32x2 %0, %1, %2, %0;" : "+l"(d) : "l"(a), "l"(b));
}
__device__ __forceinline__ void unpk2(float& lo, float& hi, uint64_t v) {
    asm("mov.b64 {%0, %1}, %2;" : "=f"(lo), "=f"(hi) : "l"(v));
}
__device__ __forceinline__ void cp16(void* dst, const void* src) {
    uint32_t d = (uint32_t)__cvta_generic_to_shared(dst);
    asm volatile("cp.async.cg.shared.global [%0], [%1], 16;\n" :: "r"(d), "l"(src) : "memory");
}
__device__ __forceinline__ void cp_commit() {
    asm volatile("cp.async.commit_group;\n" ::: "memory");
}
__device__ __forceinline__ void cp_wait0() {
    asm volatile("cp.async.wait_group 0;\n" ::: "memory");
}

// ---------------- K1: LayerNorm + QK projection ----------------
__global__ __launch_bounds__(128) void k_ln_qk(
    const float* __restrict__ x, const float* __restrict__ gamma,
    const float* __restrict__ beta, const float* __restrict__ wqk)
{
    int row = blockIdx.x;
    int t = threadIdx.x;
    __shared__ float sx[DIM], sxn[DIM], sred[2];
    if (t < DIM) sx[t] = x[row * DIM + t];
    __syncthreads();
    if (t < 32) {
        float v  = sx[t] + sx[t + 32];
        float v2 = sx[t] * sx[t] + sx[t + 32] * sx[t + 32];
        #pragma unroll
        for (int o = 16; o; o >>= 1) {
            v  += __shfl_down_sync(0xffffffffu, v,  o);
            v2 += __shfl_down_sync(0xffffffffu, v2, o);
        }
        if (t == 0) {
            float mu  = v  * (1.0f / DIM);
            float var = v2 * (1.0f / DIM) - mu * mu;
            sred[0] = mu;
            sred[1] = rsqrtf(var + 1e-5f);
        }
    }
    __syncthreads();
    if (t < DIM) {
        float xn = (sx[t] - sred[0]) * sred[1] * gamma[t] + beta[t];
        sxn[t] = xn;
        g_xn[row * DIM + t] = xn;
    }
    __syncthreads();
    float acc = 0.0f;
    #pragma unroll 16
    for (int d = 0; d < DIM; d++) acc += sxn[d] * wqk[d * 128 + t];
    int b = row / NN, n = row % NN;
    int h = (t & 63) >> 5, dh = t & 31;
    int off = ((b * HEADS + h) * NN + n) * DH + dh;
    if (t < 64) g_q[off] = acc; else g_k[off] = acc;
}

// ---------------- K2: dots + softmax ----------------
__global__ __launch_bounds__(224) void k_attn(void)
{
    int bhn = blockIdx.x;
    int n  = bhn % NN;
    int bh = bhn / NN;
    int b  = bh / HEADS;
    int h  = bh % HEADS;
    int t  = threadIdx.x;
    int wid = t >> 5, lid = t & 31;
    __shared__ float sq[DH];
    __shared__ float wred[7];
    __shared__ float sb[2];
    if (t < DH) sq[t] = g_q[(bh * NN + n) * DH + t];
    __syncthreads();
    float sc = -1e30f;
    if (t < NN) {
        const float* kr = &g_k[(bh * NN + t) * DH];
        float a = 0.0f;
        #pragma unroll
        for (int d = 0; d < DH; d++) a += sq[d] * kr[d];
        sc = a * SCALE;
    }
    float m = sc;
    #pragma unroll
    for (int o = 16; o; o >>= 1) m = fmaxf(m, __shfl_xor_sync(0xffffffffu, m, o));
    if (lid == 0) wred[wid] = m;
    __syncthreads();
    if (t == 0) {
        float mm = wred[0];
        #pragma unroll
        for (int w = 1; w < 7; w++) mm = fmaxf(mm, wred[w]);
        sb[0] = mm;
    }
    __syncthreads();
    float e = (t < NN) ? __expf(sc - sb[0]) : 0.0f;
    float s = e;
    #pragma unroll
    for (int o = 16; o; o >>= 1) s += __shfl_xor_sync(0xffffffffu, s, o);
    if (lid == 0) wred[wid] = s;
    __syncthreads();
    if (t == 0) {
        float ss = 0.0f;
        #pragma unroll
        for (int w = 0; w < 7; w++) ss += wred[w];
        sb[1] = 1.0f / ss;
    }
    __syncthreads();
    if (t < NN)
        g_attn[((n * BB + b) * HEADS + h) * NN + t] = e * sb[1];
}

// ---------------- setup: zero counters ----------------
__global__ void k_zero(void)
{
    int i = blockIdx.x * 256 + threadIdx.x;
    if (i < NU) g_cnt[i] = 0;
    if (i == NU) g_nwork = 0;
}

// ---------------- setup: inverse index map ----------------
__global__ void k_invmap(const int* __restrict__ imap)
{
    int i = blockIdx.x * 256 + threadIdx.x;
    if (i >= NN * NN) return;
    int n = i / NN, m = i - n * NN;
    int u = imap[i];
    int slot = atomicAdd(&g_cnt[u], 1);
    g_pairs[u * PCAP + slot] = (n << 8) | m;
}

// ---------------- setup: chunked work list ----------------
__global__ void k_workgen(void)
{
    int u = blockIdx.x * 256 + threadIdx.x;
    if (u >= NU) return;
    int c = g_cnt[u];
    int nch = (c + CHUNK - 1) >> 4;
    int base = atomicAdd(&g_nwork, nch);
    for (int k = 0; k < nch; k++)
        g_work[base + k] = make_int2(u, k << 4);
}

// ---------------- K3: GEMM over unique weights (dynamic smem) ----------------
__global__ __launch_bounds__(256) void k_gemm(const float* __restrict__ up)
{
    extern __shared__ __align__(16) float pool[];
    float* sW = pool + SW_OFF;       // 4096 floats
    float* sX = pool + SX_OFF;       // 128*68
    float* sA = pool + SA_OFF;       // 256
    int*   sP = (int*)(pool + SP_OFF);

    int bid = blockIdx.x;
    if (bid >= g_nwork) return;
    int2 wk = g_work[bid];
    int u = wk.x, start = wk.y;
    int len = g_cnt[u] - start;
    if (len > CHUNK) len = CHUNK;
    int t = threadIdx.x;

    if (t < len) sP[t] = g_pairs[u * PCAP + start + t];
    __syncthreads();

    // stage W (once per CTA) + xn rows for all pairs
    const float* wsrc = up + (size_t)u * 4096;
    #pragma unroll
    for (int k = 0; k < 4; k++)
        cp16(&sW[(t + 256 * k) * 4], wsrc + (t + 256 * k) * 4);
    for (int i = t; i < len * 128; i += 256) {
        int row = i >> 4, q = i & 15;
        int pi = row >> 3, b = row & 7;
        int m = sP[pi] & 255;
        cp16(&sX[row * 68 + q * 4], &g_xn[(b * NN + m) * DIM + q * 4]);
    }
    cp_commit();
    // attn scalars (plain loads)
    for (int i = t; i < len * 16; i += 256) {
        int pi = i >> 4, v = i & 15, b = v >> 1, h = v & 1;
        int code = sP[pi];
        int n = code >> 8, m = code & 255;
        sA[i] = g_attn[((n * BB + b) * HEADS + h) * NN + m];
    }
    cp_wait0();
    __syncthreads();

    int R = len * 8;
    int rg = t >> 3, eg = t & 7;
    int r0 = rg * 4, e0 = eg * 8;
    if (r0 >= R) return;

    uint64_t acc[4][4];
    #pragma unroll
    for (int j = 0; j < 4; j++)
        #pragma unroll
        for (int p = 0; p < 4; p++) acc[j][p] = 0ull;

    #pragma unroll 4
    for (int d = 0; d < DIM; d += 4) {
        float4 x4[4];
        #pragma unroll
        for (int j = 0; j < 4; j++)
            x4[j] = *(const float4*)&sX[(r0 + j) * 68 + d];
        #pragma unroll
        for (int dd = 0; dd < 4; dd++) {
            float4 wA = *(const float4*)&sW[(d + dd) * 64 + e0];
            float4 wB = *(const float4*)&sW[(d + dd) * 64 + e0 + 4];
            uint64_t w01 = pk2(wA.x, wA.y), w23 = pk2(wA.z, wA.w);
            uint64_t w45 = pk2(wB.x, wB.y), w67 = pk2(wB.z, wB.w);
            #pragma unroll
            for (int j = 0; j < 4; j++) {
                float xv = (dd == 0) ? x4[j].x : (dd == 1) ? x4[j].y
                         : (dd == 2) ? x4[j].z : x4[j].w;
                uint64_t x2 = dup2(xv);
                fma2(acc[j][0], x2, w01);
                fma2(acc[j][1], x2, w23);
                fma2(acc[j][2], x2, w45);
                fma2(acc[j][3], x2, w67);
            }
        }
    }

    // epilogue: scale by attn, write z[n][m][b][e]
    int h = eg >> 2;
    #pragma unroll
    for (int j = 0; j < 4; j++) {
        int row = r0 + j;
        int pi = row >> 3, b = row & 7;
        int code = sP[pi];
        int n = code >> 8, m = code & 255;
        float a = sA[pi * 16 + b * 2 + h];
        float y0, y1, y2, y3, y4, y5, y6, y7;
        unpk2(y0, y1, acc[j][0]);
        unpk2(y2, y3, acc[j][1]);
        unpk2(y4, y5, acc[j][2]);
        unpk2(y6, y7, acc[j][3]);
        size_t base = ((size_t)(n * NN + m)) * 512 + b * 64 + e0;
        *(float4*)&g_z[base]     = make_float4(y0 * a, y1 * a, y2 * a, y3 * a);
        *(float4*)&g_z[base + 4] = make_float4(y4 * a, y5 * a, y6 * a, y7 * a);
    }
}

// ---------------- K4: reduce over m + output projection ----------------
__global__ __launch_bounds__(512) void k_reduce(
    const float* __restrict__ wout, const float* __restrict__ bout,
    float* __restrict__ out)
{
    int n = blockIdx.x;
    int t = threadIdx.x;                   // b*64 + e
    __shared__ __align__(16) float sWo[INNER * DIM];   // 16 KB
    __shared__ float sv[512];
    #pragma unroll
    for (int k = 0; k < 2; k++)
        cp16(&sWo[(t + 512 * k) * 4], &wout[(t + 512 * k) * 4]);
    cp_commit();

    const float* zp = &g_z[(size_t)n * NN * 512 + t];
    float s0 = 0.f, s1 = 0.f, s2 = 0.f, s3 = 0.f;
    #pragma unroll 4
    for (int m = 0; m < 196; m += 4) {
        s0 += zp[(size_t)(m + 0) * 512];
        s1 += zp[(size_t)(m + 1) * 512];
        s2 += zp[(size_t)(m + 2) * 512];
        s3 += zp[(size_t)(m + 3) * 512];
    }
    s0 += zp[(size_t)196 * 512];
    sv[t] = (s0 + s1) + (s2 + s3);
    cp_wait0();
    __syncthreads();

    int b = t >> 6, d = t & 63;
    float acc = bout[d];
    #pragma unroll 16
    for (int e = 0; e < INNER; e++) acc += sv[b * 64 + e] * sWo[e * DIM + d];
    out[(b * NN + n) * DIM + d] = acc;
}

// ---------------- launch ----------------
extern "C" void kernel_launch(void* const* d_in, const int* in_sizes, int n_in,
                              void* d_out, int out_size)
{
    (void)in_sizes; (void)n_in; (void)out_size;
    const float* x     = (const float*)d_in[0];
    const float* gamma = (const float*)d_in[1];
    const float* beta  = (const float*)d_in[2];
    const float* wqk   = (const float*)d_in[3];
    const float* up    = (const float*)d_in[4];
    const float* wout  = (const float*)d_in[5];
    const float* bout  = (const float*)d_in[6];
    const int*   imap  = (const int*)d_in[7];
    float* out = (float*)d_out;

    cudaFuncSetAttribute(k_gemm, cudaFuncAttributeMaxDynamicSharedMemorySize,
                         GEMM_SMEM);

    k_ln_qk<<<BB * NN, 128>>>(x, gamma, beta, wqk);
    k_attn<<<BB * HEADS * NN, 224>>>();
    k_zero<<<5, 256>>>();
    k_invmap<<<(NN * NN + 255) / 256, 256>>>(imap);
    k_workgen<<<5, 256>>>();
    k_gemm<<<GEMMGRID, 256, GEMM_SMEM>>>(up);
    k_reduce<<<NN, 512>>>(wout, bout, out);
}